// round 2
// baseline (speedup 1.0000x reference)
#include <cuda_runtime.h>
#include <cuda_bf16.h>

namespace {

constexpr int QDIM = 21;
constexpr int NDIM = 1368;
constexpr int QN = QDIM * NDIM;          // 28728
constexpr long long OUTROW = 64000;

union U64F2 {
    unsigned long long u;
    float2 f;
};
union F4U {
    float4 f;
    unsigned long long u[2];
};

__device__ __forceinline__ unsigned long long dup2(float v) {
    unsigned long long r;
    asm("mov.b64 %0, {%1, %1};" : "=l"(r) : "f"(v));
    return r;
}
__device__ __forceinline__ void fma2(unsigned long long& acc,
                                     unsigned long long a,
                                     unsigned long long b) {
    asm("fma.rn.f32x2 %0, %1, %2, %0;" : "+l"(acc) : "l"(a), "l"(b));
}

// One 64(batch) x 64(out-dims) tile of the per-position GEMM:
//   C[b, dd] = sum_f x[b, q, start_p + j] * W[(p*D + nBase + dd), f],  f = q*W + j
// K = QDIM*W (multiple of 16). Both operands are K-contiguous.
template <int W, int LW, int S, int D, int K>
__device__ __forceinline__ void fb_body(float (*As)[68], float (*Bs)[68],
                                        const float* __restrict__ x,
                                        const float* __restrict__ Wm,
                                        float* __restrict__ out,
                                        int P, int outBase, int p, int nchunk) {
    const int nBase = nchunk * 64;
    // Last position snaps to NDIM - W (the reference's edge handling).
    const int start = (p == P - 1) ? (NDIM - W) : p * S;

    const int tid = threadIdx.x;
    const int tx = tid & 31;   // 2 output cols per thread
    const int ty = tid >> 5;   // 8 output rows per thread

    // Loader mapping: 256 threads load a 64x16 tile as one float4 each.
    const int lrow = tid >> 2;        // 0..63
    const int lk = (tid & 3) << 2;    // 0,4,8,12

    const float* xrow = x + (size_t)lrow * QN + start;
    const float* wrow = Wm + ((size_t)p * D + nBase + lrow) * (size_t)K;

    // acc[mi][j]: packed pair of rows (8*ty + 2*mi, +1) at col (2*tx + j)
    unsigned long long acc[4][2];
#pragma unroll
    for (int i = 0; i < 4; ++i) { acc[i][0] = 0ull; acc[i][1] = 0ull; }

    // Prefetch first K-tile. A float4 never crosses a q boundary:
    // lk % 4 == 0 and W % 4 == 0; addresses are 16B aligned (start % 4 == 0).
    {
        const int ka = lk;
        // first tile: k0 = 0, so q/j derived from ka directly
        float4 av = *(const float4*)(xrow + (ka >> LW) * NDIM + (ka & (W - 1)));
        float4 bv = *(const float4*)(wrow + lk);

        for (int k0 = 0; k0 < K; k0 += 16) {
            As[lk + 0][lrow] = av.x;
            As[lk + 1][lrow] = av.y;
            As[lk + 2][lrow] = av.z;
            As[lk + 3][lrow] = av.w;
            Bs[lk + 0][lrow] = bv.x;
            Bs[lk + 1][lrow] = bv.y;
            Bs[lk + 2][lrow] = bv.z;
            Bs[lk + 3][lrow] = bv.w;
            __syncthreads();

            if (k0 + 16 < K) {
                const int kn = k0 + 16 + lk;
                av = *(const float4*)(xrow + (kn >> LW) * NDIM + (kn & (W - 1)));
                bv = *(const float4*)(wrow + k0 + 16 + lk);
            }

#pragma unroll
            for (int k = 0; k < 16; ++k) {
                F4U aLo, aHi;
                aLo.f = *(const float4*)&As[k][8 * ty];       // rows 8ty..8ty+3
                aHi.f = *(const float4*)&As[k][8 * ty + 4];   // rows 8ty+4..8ty+7
                const float2 bp = *(const float2*)&Bs[k][2 * tx];
                const unsigned long long b0 = dup2(bp.x);
                const unsigned long long b1 = dup2(bp.y);
                fma2(acc[0][0], aLo.u[0], b0);
                fma2(acc[0][1], aLo.u[0], b1);
                fma2(acc[1][0], aLo.u[1], b0);
                fma2(acc[1][1], aLo.u[1], b1);
                fma2(acc[2][0], aHi.u[0], b0);
                fma2(acc[2][1], aHi.u[0], b1);
                fma2(acc[3][0], aHi.u[1], b0);
                fma2(acc[3][1], aHi.u[1], b1);
            }
            __syncthreads();
        }
    }

    // Epilogue: out[b, outBase + p*D + nBase + col]
    const long long col = (long long)outBase + (long long)p * D + nBase + 2 * tx;
#pragma unroll
    for (int mi = 0; mi < 4; ++mi) {
        U64F2 v0, v1;
        v0.u = acc[mi][0];
        v1.u = acc[mi][1];
        const int m0 = 8 * ty + 2 * mi;
        float* o0 = out + (long long)m0 * OUTROW + col;
        *(float2*)o0 = make_float2(v0.f.x, v1.f.x);              // row m0
        *(float2*)(o0 + OUTROW) = make_float2(v0.f.y, v1.f.y);   // row m0+1
    }
}

// Grid: 1000 blocks. Longest-K tiles (scale 2, K=1344) scheduled first.
//   [0, 328):   scale 2 (w=64,s=16,d=256,P=82),  4 n-chunks per position
//   [328, 662): scale 1 (w=32,s=8, d=128,P=167), 2 n-chunks per position
//   [662,1000): scale 0 (w=16,s=4, d=64, P=338), 1 n-chunk per position
__global__ __launch_bounds__(256)
void fb_all_kernel(const float* __restrict__ x,
                   const float* __restrict__ w0,
                   const float* __restrict__ w1,
                   const float* __restrict__ w2,
                   float* __restrict__ out) {
    __shared__ float As[16][68];
    __shared__ float Bs[16][68];

    const int bid = blockIdx.x;
    if (bid < 328) {
        fb_body<64, 6, 16, 256, 1344>(As, Bs, x, w2, out, 82, 43008, bid >> 2, bid & 3);
    } else if (bid < 662) {
        const int b = bid - 328;
        fb_body<32, 5, 8, 128, 672>(As, Bs, x, w1, out, 167, 21632, b >> 1, b & 1);
    } else {
        const int b = bid - 662;
        fb_body<16, 4, 4, 64, 336>(As, Bs, x, w0, out, 338, 0, b, 0);
    }
}

}  // namespace

extern "C" void kernel_launch(void* const* d_in, const int* in_sizes, int n_in,
                              void* d_out, int out_size) {
    const float* x = (const float*)d_in[0];
    const float* w0 = (const float*)d_in[1];
    const float* w1 = (const float*)d_in[2];
    const float* w2 = (const float*)d_in[3];
    float* out = (float*)d_out;
    fb_all_kernel<<<1000, 256>>>(x, w0, w1, w2, out);
}

// round 15
// speedup vs baseline: 1.9374x; 1.9374x over previous
#include <cuda_runtime.h>
#include <cstdint>

namespace {

constexpr int QDIM = 21;
constexpr int NDIM = 1368;
constexpr int QN = QDIM * NDIM;      // 28728
constexpr long long OUTROW = 64000;

__device__ __forceinline__ float tf32r(float f) {
    float r;
    asm("cvt.rna.tf32.f32 %0, %1;" : "=f"(r) : "f"(f));
    return r;
}

__device__ __forceinline__ void mma8(float* c, uint32_t a0, uint32_t a1,
                                     uint32_t a2, uint32_t a3,
                                     uint32_t b0, uint32_t b1) {
    asm volatile(
        "mma.sync.aligned.m16n8k8.row.col.f32.tf32.tf32.f32 "
        "{%0,%1,%2,%3}, {%4,%5,%6,%7}, {%8,%9}, {%0,%1,%2,%3};"
        : "+f"(c[0]), "+f"(c[1]), "+f"(c[2]), "+f"(c[3])
        : "r"(a0), "r"(a1), "r"(a2), "r"(a3), "r"(b0), "r"(b1));
}

// One 64(batch) x 64(outdim) tile: C[m][n] = sum_k x[m][k_f] * W[n][k_f].
// smem layout: row-major [64][STR], k permuted as pos = (KC/4)*(k%4) + k/4 so
// that an aligned float4 at col (KC/4)*c (+4*ks2) yields the tf32 fragment
// elements for two consecutive k8-steps.
//   KC=32 -> STR=36 (144B % 128 = 16; conflict-free LDS.128 vs 32B c-span)
//   KC=16 -> STR=48 (192B % 128 = 64; conflict-free vs 16B c-span)
template <int KC, int STR, int W, int LW, int K>
__device__ __forceinline__ void fb_tile(float* __restrict__ As,
                                        float* __restrict__ Bs,
                                        const float* __restrict__ x,
                                        const float* __restrict__ Wm,
                                        float* __restrict__ out,
                                        int P, int outBase, int D,
                                        int p, int nBase) {
    constexpr int NC = K / KC;
    constexpr int NV = KC / 16;   // float4 loads per array per thread
    constexpr int QW = KC / 4;    // 4-float groups per row
    static_assert(K % KC == 0, "K divisible by chunk");

    const int start = (p == P - 1) ? (NDIM - W) : p * (W / 4);
    const int tid = threadIdx.x;
    const int warp = tid >> 5, lane = tid & 31;
    const int g = lane >> 2, cx = lane & 3;
    const int m0 = (warp & 1) * 32;    // batch-row block
    const int n0 = (warp >> 1) * 16;   // outdim block

    const float* wb = Wm + ((size_t)p * D + nBase) * (size_t)K;

    float acc[2][2][4];
#pragma unroll
    for (int a = 0; a < 2; ++a)
#pragma unroll
        for (int b = 0; b < 2; ++b)
#pragma unroll
            for (int c = 0; c < 4; ++c) acc[a][b][c] = 0.f;

    int lrow[NV], lq[NV];
#pragma unroll
    for (int j = 0; j < NV; ++j) {
        int v = tid + 256 * j;
        lrow[j] = v / QW;
        lq[j] = v % QW;
    }

    // Prefetch chunk 0. float4 never crosses a window-q boundary:
    // k % 4 == 0 and W % 4 == 0; x starts are 16B aligned.
    float4 av[NV], bv[NV];
#pragma unroll
    for (int j = 0; j < NV; ++j) {
        int k = 4 * lq[j];
        bv[j] = *(const float4*)(wb + (size_t)lrow[j] * K + k);
        int q = k >> LW, off = k & (W - 1);
        av[j] = *(const float4*)(x + (size_t)lrow[j] * QN + q * NDIM + start + off);
    }

    for (int i = 0; i < NC; ++i) {
        // round to tf32 and store permuted
#pragma unroll
        for (int j = 0; j < NV; ++j) {
            const float* ap = &av[j].x;
            const float* bp = &bv[j].x;
            const int base = lrow[j] * STR + lq[j];
#pragma unroll
            for (int jj = 0; jj < 4; ++jj) {
                As[base + QW * jj] = tf32r(ap[jj]);
                Bs[base + QW * jj] = tf32r(bp[jj]);
            }
        }
        __syncthreads();

        if (i + 1 < NC) {
            const int k0 = (i + 1) * KC;
#pragma unroll
            for (int j = 0; j < NV; ++j) {
                int k = k0 + 4 * lq[j];
                bv[j] = *(const float4*)(wb + (size_t)lrow[j] * K + k);
                int q = k >> LW, off = k & (W - 1);
                av[j] = *(const float4*)(x + (size_t)lrow[j] * QN + q * NDIM + start + off);
            }
        }

#pragma unroll
        for (int ks2 = 0; ks2 < NV; ++ks2) {
            const int colA = QW * cx + 4 * ks2;
            float4 al[2], ah[2], bf[2];
#pragma unroll
            for (int mt = 0; mt < 2; ++mt) {
                al[mt] = *(const float4*)&As[(m0 + 16 * mt + g) * STR + colA];
                ah[mt] = *(const float4*)&As[(m0 + 16 * mt + g + 8) * STR + colA];
            }
#pragma unroll
            for (int nt = 0; nt < 2; ++nt)
                bf[nt] = *(const float4*)&Bs[(n0 + 8 * nt + g) * STR + colA];

#pragma unroll
            for (int u = 0; u < 2; ++u) {
#pragma unroll
                for (int mt = 0; mt < 2; ++mt) {
                    const float* alp = &al[mt].x;
                    const float* ahp = &ah[mt].x;
                    const uint32_t a0 = __float_as_uint(alp[2 * u]);
                    const uint32_t a1 = __float_as_uint(ahp[2 * u]);
                    const uint32_t a2 = __float_as_uint(alp[2 * u + 1]);
                    const uint32_t a3 = __float_as_uint(ahp[2 * u + 1]);
#pragma unroll
                    for (int nt = 0; nt < 2; ++nt) {
                        const float* bp = &bf[nt].x;
                        mma8(acc[mt][nt], a0, a1, a2, a3,
                             __float_as_uint(bp[2 * u]),
                             __float_as_uint(bp[2 * u + 1]));
                    }
                }
            }
        }
        __syncthreads();
    }

    // Epilogue: C row = batch, C col = outdim. float2 stores (8B aligned).
    const long long colB = (long long)outBase + (long long)p * D + nBase + n0 + 2 * cx;
#pragma unroll
    for (int mt = 0; mt < 2; ++mt) {
        const int row = m0 + 16 * mt + g;
#pragma unroll
        for (int nt = 0; nt < 2; ++nt) {
            float* o = out + (long long)row * OUTROW + colB + 8 * nt;
            *(float2*)o = make_float2(acc[mt][nt][0], acc[mt][nt][1]);
            *(float2*)(o + 8 * OUTROW) = make_float2(acc[mt][nt][2], acc[mt][nt][3]);
        }
    }
}

// Grid: 1000 CTAs, longest-K first.
//   [0,328):   scale2 w=64 s=16 d=256 P=82  K=1344 (4 n-chunks/pos)
//   [328,662): scale1 w=32 s=8  d=128 P=167 K=672  (2 n-chunks/pos)
//   [662,1000):scale0 w=16 s=4  d=64  P=338 K=336  (KC=16; 336 % 32 != 0)
__global__ __launch_bounds__(256)
void fb_all_kernel(const float* __restrict__ x,
                   const float* __restrict__ w0,
                   const float* __restrict__ w1,
                   const float* __restrict__ w2,
                   float* __restrict__ out) {
    __shared__ float As[64 * 48];
    __shared__ float Bs[64 * 48];

    const int bid = blockIdx.x;
    if (bid < 328) {
        fb_tile<32, 36, 64, 6, 1344>(As, Bs, x, w2, out, 82, 43008, 256,
                                     bid >> 2, (bid & 3) * 64);
    } else if (bid < 662) {
        const int b = bid - 328;
        fb_tile<32, 36, 32, 5, 672>(As, Bs, x, w1, out, 167, 21632, 128,
                                    b >> 1, (b & 1) * 64);
    } else {
        const int b = bid - 662;
        fb_tile<16, 48, 16, 4, 336>(As, Bs, x, w0, out, 338, 0, 64, b, 0);
    }
}

}  // namespace

extern "C" void kernel_launch(void* const* d_in, const int* in_sizes, int n_in,
                              void* d_out, int out_size) {
    const float* x = (const float*)d_in[0];
    const float* w0 = (const float*)d_in[1];
    const float* w1 = (const float*)d_in[2];
    const float* w2 = (const float*)d_in[3];
    float* out = (float*)d_out;
    fb_all_kernel<<<1000, 256>>>(x, w0, w1, w2, out);
}